// round 4
// baseline (speedup 1.0000x reference)
#include <cuda_runtime.h>
#include <math.h>

typedef unsigned long long ull;

#define Bv 32
#define Lv 1024
#define Hv 512
#define NGROUP 8
#define CPG 16
#define ROWP 516   // padded row stride (floats) in smem

// ---------------- device scratch (no cudaMalloc allowed) ----------------
__device__ float g_pre[(size_t)Lv * Bv * 1536];   // [t][b][0..1023]=x_ru+b_ru, [1024..1535]=x_c+b_c
__device__ float g_h [Bv * Hv];                   // h[b][j]
__device__ float g_rh[Bv * Hv];                   // (r*h)[b][j]
__device__ float g_z [Bv * Hv];                   // z[b][n]
__device__ unsigned int g_flag[NGROUP * CPG];

// ---------------- f32x2 helpers ----------------
__device__ __forceinline__ ull splat2(float x) {
    ull r; asm("mov.b64 %0, {%1, %1};" : "=l"(r) : "f"(x)); return r;
}
__device__ __forceinline__ float2 unpack2(ull v) {
    float2 f; asm("mov.b64 {%0, %1}, %2;" : "=f"(f.x), "=f"(f.y) : "l"(v)); return f;
}
__device__ __forceinline__ void ffma2(ull& d, ull a, ull b) {
    asm("fma.rn.f32x2 %0, %1, %2, %0;" : "+l"(d) : "l"(a), "l"(b));
}
__device__ __forceinline__ unsigned smaddr(const void* p) {
    unsigned r;
    asm("{.reg .u64 t; cvta.to.shared.u64 t, %1; cvt.u32.u64 %0, t;}" : "=r"(r) : "l"(p));
    return r;
}

#define LDS2O(r0, r1, A, O) \
    asm volatile("ld.shared.v2.b64 {%0,%1},[%2+" O "];" : "=l"(r0), "=l"(r1) : "r"(A))

// 16 floats of w x 16 floats of h -> 8 FFMA2 into 4 rotating accumulators
#define DOT16(wa, ha, a0, a1, a2, a3) do {                          \
    ull w0,w1,w2,w3,w4,w5,w6,w7,h0,h1,h2,h3,h4,h5,h6,h7;           \
    LDS2O(w0,w1,(wa),"0");  LDS2O(h0,h1,(ha),"0");                  \
    LDS2O(w2,w3,(wa),"16"); LDS2O(h2,h3,(ha),"16");                 \
    LDS2O(w4,w5,(wa),"32"); LDS2O(h4,h5,(ha),"32");                 \
    LDS2O(w6,w7,(wa),"48"); LDS2O(h6,h7,(ha),"48");                 \
    ffma2(a0,w0,h0); ffma2(a1,w1,h1); ffma2(a2,w2,h2); ffma2(a3,w3,h3); \
    ffma2(a0,w4,h4); ffma2(a1,w5,h5); ffma2(a2,w6,h6); ffma2(a3,w7,h7); \
} while (0)

// ---------------- kernel 0: reset flags + h ----------------
__global__ void init_kernel(const float* __restrict__ init_h) {
    int i = blockIdx.x * 256 + threadIdx.x;
    if (i < Bv * Hv) g_h[i] = init_h[i];
    if (i < NGROUP * CPG) g_flag[i] = 0u;
}

// ---------------- kernel 1: projection GEMM ----------------
// pre[t][b][n] = x[b,t,:] . Wx[n,:] + bias[n],  Wx row n = W[n][512..1023]
// C tile 64m x 64n, K-tile 32, 256 threads, 4m x 4n micro via f32x2, double buffered.
__global__ void __launch_bounds__(256) gemm_pre(const float* __restrict__ x,
                                                const float* __restrict__ W_ru,
                                                const float* __restrict__ W_c,
                                                const float* __restrict__ b_ru,
                                                const float* __restrict__ b_c) {
    __shared__ float As[2][64 * 36];
    __shared__ float Bs[2][32 * 64];
    const int tid = threadIdx.x;
    const int n0 = blockIdx.x * 64;
    const int m0 = blockIdx.y * 64;

    const float* Wsrc = (n0 < 1024) ? (W_ru + (size_t)n0 * 1024 + 512)
                                    : (W_c + (size_t)(n0 - 1024) * 1024 + 512);

    const int arow = tid >> 3, ac = (tid & 7) * 4;       // A loader: 2 x (32 rows x 32 cols)
    const float* Ap0 = x + (size_t)(m0 + arow) * 512 + ac;
    const int bn = tid & 63, bk = (tid >> 6) * 4;        // B loader: 64 n rows, 2 float4 along k
    const float* Bp0 = Wsrc + (size_t)bn * 1024 + bk;

    const int tx = tid & 15, ty = tid >> 4;

    ull acc[4][2];
#pragma unroll
    for (int i = 0; i < 4; i++) { acc[i][0] = 0ull; acc[i][1] = 0ull; }

    float4 ra0 = *(const float4*)(Ap0);
    float4 ra1 = *(const float4*)(Ap0 + 32 * 512);
    float4 rb0 = *(const float4*)(Bp0);
    float4 rb1 = *(const float4*)(Bp0 + 16);

    *(float4*)&As[0][arow * 36 + ac] = ra0;
    *(float4*)&As[0][(arow + 32) * 36 + ac] = ra1;
    Bs[0][(bk + 0) * 64 + bn] = rb0.x; Bs[0][(bk + 1) * 64 + bn] = rb0.y;
    Bs[0][(bk + 2) * 64 + bn] = rb0.z; Bs[0][(bk + 3) * 64 + bn] = rb0.w;
    Bs[0][(bk + 16) * 64 + bn] = rb1.x; Bs[0][(bk + 17) * 64 + bn] = rb1.y;
    Bs[0][(bk + 18) * 64 + bn] = rb1.z; Bs[0][(bk + 19) * 64 + bn] = rb1.w;
    __syncthreads();

    for (int kt = 0; kt < 16; kt++) {
        const int cur = kt & 1;
        if (kt < 15) {
            const float* ap = Ap0 + (kt + 1) * 32;
            ra0 = *(const float4*)(ap);
            ra1 = *(const float4*)(ap + 32 * 512);
            const float* bp = Bp0 + (kt + 1) * 32;
            rb0 = *(const float4*)(bp);
            rb1 = *(const float4*)(bp + 16);
        }
        const float* Arow = &As[cur][ty * 4 * 36];
        const float* Bbase = &Bs[cur][0];
#pragma unroll
        for (int kk = 0; kk < 32; kk++) {
            float av0 = Arow[kk], av1 = Arow[36 + kk], av2 = Arow[72 + kk], av3 = Arow[108 + kk];
            const ull* Bq = (const ull*)(Bbase + kk * 64);
            ull b0 = Bq[tx * 2], b1 = Bq[tx * 2 + 1];
            ull s0 = splat2(av0), s1 = splat2(av1), s2 = splat2(av2), s3 = splat2(av3);
            ffma2(acc[0][0], s0, b0); ffma2(acc[0][1], s0, b1);
            ffma2(acc[1][0], s1, b0); ffma2(acc[1][1], s1, b1);
            ffma2(acc[2][0], s2, b0); ffma2(acc[2][1], s2, b1);
            ffma2(acc[3][0], s3, b0); ffma2(acc[3][1], s3, b1);
        }
        if (kt < 15) {
            const int nb = (kt + 1) & 1;
            *(float4*)&As[nb][arow * 36 + ac] = ra0;
            *(float4*)&As[nb][(arow + 32) * 36 + ac] = ra1;
            Bs[nb][(bk + 0) * 64 + bn] = rb0.x; Bs[nb][(bk + 1) * 64 + bn] = rb0.y;
            Bs[nb][(bk + 2) * 64 + bn] = rb0.z; Bs[nb][(bk + 3) * 64 + bn] = rb0.w;
            Bs[nb][(bk + 16) * 64 + bn] = rb1.x; Bs[nb][(bk + 17) * 64 + bn] = rb1.y;
            Bs[nb][(bk + 18) * 64 + bn] = rb1.z; Bs[nb][(bk + 19) * 64 + bn] = rb1.w;
        }
        __syncthreads();
    }

    const float* bias = (n0 < 1024) ? (b_ru + n0) : (b_c + (n0 - 1024));
    const float4 bv = *(const float4*)&bias[tx * 4];
#pragma unroll
    for (int i = 0; i < 4; i++) {
        int m = m0 + ty * 4 + i;
        int bb = m >> 10, tt = m & 1023;
        float2 f0 = unpack2(acc[i][0]);
        float2 f1 = unpack2(acc[i][1]);
        float4 o = make_float4(f0.x + bv.x, f0.y + bv.y, f1.x + bv.z, f1.y + bv.w);
        *(float4*)&g_pre[((size_t)tt * 32 + bb) * 1536 + n0 + tx * 4] = o;
    }
}

// ---------------- group barrier helpers ----------------
__device__ __forceinline__ void flag_signal_wait(int grp, int c, unsigned val) {
    __syncthreads();
    if (threadIdx.x == 0) {
        asm volatile("fence.acq_rel.gpu;" ::: "memory");
        asm volatile("st.relaxed.gpu.u32 [%0], %1;"
                     :: "l"(&g_flag[grp * CPG + c]), "r"(val) : "memory");
    }
    if (threadIdx.x < CPG) {
        const unsigned* fp = &g_flag[grp * CPG + threadIdx.x];
        unsigned v;
        do {
            asm volatile("ld.acquire.gpu.u32 %0, [%1];" : "=r"(v) : "l"(fp) : "memory");
        } while (v < val);
    }
    __syncthreads();
}

// ---------------- kernel 2: persistent recurrent scan ----------------
// 128 CTAs = 8 groups x 16 CTAs, 256 threads, ~210KB dynamic smem (1 CTA/SM).
// CTA c of a group: gate rows [c*64, c*64+64), cand rows [c*32, c*32+32), 4 batches.
__global__ void __launch_bounds__(256, 1) scan_kernel(const float* __restrict__ W_ru,
                                                      const float* __restrict__ W_c,
                                                      float* __restrict__ out,
                                                      int has_last) {
    extern __shared__ float sm[];
    float* sWg = sm;                      // 64 x ROWP  (Wh_ru rows)
    float* sWc = sWg + 64 * ROWP;         // 32 x ROWP  (Wh_c rows)
    float* sh  = sWc + 32 * ROWP;         // 4 x ROWP
    float* srh = sh + 4 * ROWP;           // 4 x ROWP

    const int tid = threadIdx.x;
    const int grp = blockIdx.x >> 4;
    const int c   = blockIdx.x & 15;

    // --- load recurrent weights (cols 0..511 of W rows) into smem ---
    {
        const int gbase = c * 64;
        for (int i = tid; i < 64 * 128; i += 256) {
            int r = i >> 7, q = (i & 127) * 4;
            float4 v = *(const float4*)(W_ru + (size_t)(gbase + r) * 1024 + q);
            *(float4*)(sWg + r * ROWP + q) = v;
        }
        const int nbase = c * 32;
        for (int i = tid; i < 32 * 128; i += 256) {
            int r = i >> 7, q = (i & 127) * 4;
            float4 v = *(const float4*)(W_c + (size_t)(nbase + r) * 1024 + q);
            *(float4*)(sWc + r * ROWP + q) = v;
        }
    }
    // --- stage initial h ---
    for (int i = tid; i < 4 * 128; i += 256) {
        int b = i >> 7, q = (i & 127) * 4;
        float4 v = __ldcg((const float4*)(g_h + (size_t)(grp * 4 + b) * 512 + q));
        *(float4*)(sh + b * ROWP + q) = v;
    }
    __syncthreads();

    // phase-1 thread mapping: one (gate row, batch) per thread
    const int gl  = tid >> 2;             // 0..63
    const int bl  = tid & 3;
    const int ggl = c * 64 + gl;          // global gate row 0..1023
    const int gb  = grp * 4 + bl;         // global batch
    const unsigned wg_base = smaddr(sWg + gl * ROWP);
    const unsigned sh_base = smaddr(sh + bl * ROWP);

    // phase-2 thread mapping: 2 threads per (cand row, batch)
    const int d    = tid >> 1;
    const int half = tid & 1;
    const int nl   = d >> 2;              // 0..31
    const int bl2  = d & 3;
    const int n    = c * 32 + nl;
    const int gb2  = grp * 4 + bl2;
    const unsigned wc_base  = smaddr(sWc + nl * ROWP + half * 256);
    const unsigned srh_base = smaddr(srh + bl2 * ROWP + half * 256);

    for (int t = 0; t < Lv; t++) {
        // ---- phase 1: gates ----
        float xg = __ldg(&g_pre[((size_t)t * 32 + gb) * 1536 + ggl]);
        ull a0 = 0, a1 = 0, a2 = 0, a3 = 0;
        {
            unsigned wa = wg_base, ha = sh_base;
#pragma unroll
            for (int i = 0; i < 32; i++) {
                DOT16(wa, ha, a0, a1, a2, a3);
                wa += 64; ha += 64;
            }
        }
        float2 f0 = unpack2(a0), f1 = unpack2(a1), f2 = unpack2(a2), f3 = unpack2(a3);
        float pre = ((f0.x + f0.y) + (f1.x + f1.y)) + ((f2.x + f2.y) + (f3.x + f3.y)) + xg;
        float gate = 1.0f / (1.0f + expf(-pre));
        if (ggl < 512) {
            float rhv = gate * sh[bl * ROWP + ggl];
            __stcg(&g_rh[(size_t)gb * 512 + ggl], rhv);
        } else {
            __stcg(&g_z[(size_t)gb * 512 + (ggl - 512)], gate);
        }

        flag_signal_wait(grp, c, 2u * t + 1u);

        // ---- stage rh ----
        for (int i = tid; i < 512; i += 256) {
            int b = i >> 7, q = (i & 127) * 4;
            float4 v = __ldcg((const float4*)(g_rh + (size_t)(grp * 4 + b) * 512 + q));
            *(float4*)(srh + b * ROWP + q) = v;
        }
        __syncthreads();

        // ---- phase 2: candidate + blend ----
        float xc = __ldg(&g_pre[((size_t)t * 32 + gb2) * 1536 + 1024 + n]);
        float zv = __ldcg(&g_z[(size_t)gb2 * 512 + n]);
        ull c0 = 0, c1 = 0, c2 = 0, c3 = 0;
        {
            unsigned wa = wc_base, ha = srh_base;
#pragma unroll
            for (int i = 0; i < 16; i++) {
                DOT16(wa, ha, c0, c1, c2, c3);
                wa += 64; ha += 64;
            }
        }
        float2 g0 = unpack2(c0), g1 = unpack2(c1), g2 = unpack2(c2), g3 = unpack2(c3);
        float tot = ((g0.x + g0.y) + (g1.x + g1.y)) + ((g2.x + g2.y) + (g3.x + g3.y));
        tot += __shfl_xor_sync(0xffffffffu, tot, 1);
        if (half == 0) {
            float cand = tanhf(tot + xc);
            float hold = sh[bl2 * ROWP + n];
            float hnew = hold + zv * (cand - hold);       // (1-z)*h + z*cand
            __stcg(&g_h[(size_t)gb2 * 512 + n], hnew);
            out[(size_t)gb2 * ((size_t)Lv * 512) + (size_t)t * 512 + n] = hnew;
            if (has_last && t == Lv - 1)
                out[(size_t)Bv * Lv * 512 + (size_t)gb2 * 512 + n] = hnew;
        }

        flag_signal_wait(grp, c, 2u * t + 2u);

        // ---- restage h for next step ----
        if (t < Lv - 1) {
            for (int i = tid; i < 512; i += 256) {
                int b = i >> 7, q = (i & 127) * 4;
                float4 v = __ldcg((const float4*)(g_h + (size_t)(grp * 4 + b) * 512 + q));
                *(float4*)(sh + b * ROWP + q) = v;
            }
            __syncthreads();
        }
    }
}

// ---------------- launch ----------------
extern "C" void kernel_launch(void* const* d_in, const int* in_sizes, int n_in,
                              void* d_out, int out_size) {
    const float* x      = (const float*)d_in[0];
    const float* init_h = (const float*)d_in[1];
    const float* W_ru   = (const float*)d_in[2];
    const float* b_ru   = (const float*)d_in[3];
    const float* W_c    = (const float*)d_in[4];
    const float* b_c    = (const float*)d_in[5];
    float* out = (float*)d_out;

    const int smem_bytes = (64 * ROWP + 32 * ROWP + 8 * ROWP) * 4;  // 214,656 B
    cudaFuncSetAttribute(scan_kernel, cudaFuncAttributeMaxDynamicSharedMemorySize, smem_bytes);

    int has_last = (out_size >= Bv * Lv * Hv + Bv * Hv) ? 1 : 0;

    init_kernel<<<64, 256>>>(init_h);
    gemm_pre<<<dim3(24, 512), 256>>>(x, W_ru, W_c, b_ru, b_c);
    scan_kernel<<<NGROUP * CPG, 256, smem_bytes>>>(W_ru, W_c, out, has_last);
}